// round 3
// baseline (speedup 1.0000x reference)
#include <cuda_runtime.h>
#include <cstdint>

#define MAXN   50000
#define KNB    32
#define INC    128
#define H      64
#define EDGED  32
#define H2     128
#define NBMAX  782   // ceil(MAXN/64)

// ---------------- scratch (static device memory; no allocation) ----------------
__device__ float g_proj[(size_t)MAXN * 128];   // [n][0..63]=x@w_src.T, [64..127]=x@w_dst.T
__device__ float g_out [(size_t)MAXN * H];     // aggregated node features
__device__ float g_h   [(size_t)MAXN * H2];    // MLP hidden
__device__ float g_part[2 * NBMAX * H2];       // BN partial sums / sumsq (per mlp1 block)
__device__ float g_sb  [2 * H2];               // BN scale, bias

// ---------------- f32x2 packed math helpers (sm_100+) ----------------
__device__ __forceinline__ void ffma2(unsigned long long& acc,
                                      unsigned long long a,
                                      unsigned long long b) {
    asm("fma.rn.f32x2 %0, %1, %2, %0;" : "+l"(acc) : "l"(a), "l"(b));
}
__device__ __forceinline__ unsigned long long fadd2(unsigned long long a,
                                                    unsigned long long b) {
    unsigned long long d;
    asm("add.rn.f32x2 %0, %1, %2;" : "=l"(d) : "l"(a), "l"(b));
    return d;
}
__device__ __forceinline__ float f2sum(unsigned long long v) {
    float lo, hi;
    asm("mov.b64 {%0, %1}, %2;" : "=f"(lo), "=f"(hi) : "l"(v));
    return lo + hi;
}

// =====================================================================
// Kernel A: g_proj[n][c] = x[n] . W[c]  (W = [w_src ; w_dst], 128x128)
// block 256 thr; tile 64 nodes x 128 ch; thread 4 nodes x 8 ch.
// A row-major in shared, B straight from global (L1-hot), d-packed f32x2.
// =====================================================================
__global__ void __launch_bounds__(256)
proj_kernel(const float* __restrict__ x,
            const float* __restrict__ w_src,
            const float* __restrict__ w_dst, int n)
{
    __shared__ __align__(16) float xs[64][36];
    const int t  = threadIdx.x;
    const int tx = t & 15, ty = t >> 4;
    const int n0 = blockIdx.x * 64;

    const float* wbase = (tx < 8) ? (w_src + (size_t)(tx * 8) * 128)
                                  : (w_dst + (size_t)(tx * 8 - 64) * 128);

    unsigned long long acc2[4][8];
#pragma unroll
    for (int i = 0; i < 4; i++)
#pragma unroll
        for (int j = 0; j < 8; j++) acc2[i][j] = 0ull;

    for (int dt = 0; dt < 128; dt += 32) {
        // stage x tile (64 rows x 32 d), row-major
#pragma unroll
        for (int it = 0; it < 2; it++) {
            int idx = t + it * 256;
            int row = idx >> 3, q = idx & 7;
            int gn  = n0 + row;
            float4 v = make_float4(0.f, 0.f, 0.f, 0.f);
            if (gn < n) v = *(const float4*)&x[(size_t)gn * 128 + dt + q * 4];
            *(float4*)&xs[row][q * 4] = v;
        }
        __syncthreads();

#pragma unroll
        for (int dq = 0; dq < 32; dq += 4) {
            ulonglong2 av[4];
#pragma unroll
            for (int i = 0; i < 4; i++)
                av[i] = *(const ulonglong2*)&xs[ty * 4 + i][dq];
#pragma unroll
            for (int j = 0; j < 8; j++) {
                ulonglong2 bv = *(const ulonglong2*)(wbase + (size_t)j * 128 + dt + dq);
#pragma unroll
                for (int i = 0; i < 4; i++) {
                    ffma2(acc2[i][j], av[i].x, bv.x);
                    ffma2(acc2[i][j], av[i].y, bv.y);
                }
            }
        }
        __syncthreads();
    }
#pragma unroll
    for (int i = 0; i < 4; i++) {
        int gn = n0 + ty * 4 + i;
        if (gn < n) {
            float o[8];
#pragma unroll
            for (int j = 0; j < 8; j++) o[j] = f2sum(acc2[i][j]);
            *(float4*)&g_proj[(size_t)gn * 128 + tx * 8] =
                make_float4(o[0], o[1], o[2], o[3]);
            *(float4*)&g_proj[(size_t)gn * 128 + tx * 8 + 4] =
                make_float4(o[4], o[5], o[6], o[7]);
        }
    }
}

// =====================================================================
// Kernel B: per-edge MLP + per-destination softmax aggregation.
// block 128 thr = 2 nodes; thread = (node, channel h); softmax thread-local.
// Edge GEMM dot products use f32x2 packed FMAs over d.
// =====================================================================
__global__ void __launch_bounds__(128)
edge_kernel(const float* __restrict__ ea,
            const float* __restrict__ w_edge,
            const int*   __restrict__ ei,   // edge_index row 0 (src)
            const int*   __restrict__ nbr,
            int n)
{
    __shared__ __align__(16) float sea[2][KNB][EDGED];
    __shared__ int      se_[2][KNB];
    __shared__ int      ss_[2][KNB];
    __shared__ unsigned smask[2];

    const int local = threadIdx.x >> 6;   // node slot in block
    const int h     = threadIdx.x & 63;   // channel
    const int node  = blockIdx.x * 2 + local;
    const bool active = (node < n);

    if (h < 32) {
        int e = -1;
        if (active) e = nbr[(size_t)node * KNB + h];
        se_[local][h] = e;
        ss_[local][h] = (e >= 0) ? ei[e] : 0;
        unsigned msk = __ballot_sync(0xffffffffu, e >= 0);
        if (h == 0) smask[local] = msk;
    }
    __syncthreads();
    const unsigned vm = smask[local];

    // stage edge_attr rows (32 x 32 f32 per node) into shared
    for (int i = h; i < KNB * 8; i += 64) {
        int k = i >> 3, q = i & 7;
        float4 v = make_float4(0.f, 0.f, 0.f, 0.f);
        if ((vm >> k) & 1)
            v = *(const float4*)&ea[(size_t)se_[local][k] * EDGED + q * 4];
        *(float4*)&sea[local][k][q * 4] = v;
    }
    __syncthreads();

    // this thread's w_edge row (channel h) as 16 packed f32x2
    unsigned long long wp[16];
    {
        const ulonglong2* wr = (const ulonglong2*)&w_edge[(size_t)h * EDGED];
#pragma unroll
        for (int i = 0; i < 8; i++) {
            ulonglong2 v = wr[i];
            wp[2 * i]     = v.x;
            wp[2 * i + 1] = v.y;
        }
    }

    float m[KNB];
#pragma unroll
    for (int k = 0; k < KNB; k++) {
        const ulonglong2* row = (const ulonglong2*)sea[local][k];
        unsigned long long a0 = 0ull, a1 = 0ull;
#pragma unroll
        for (int i = 0; i < 8; i++) {
            ulonglong2 v = row[i];
            ffma2(a0, v.x, wp[2 * i]);
            ffma2(a1, v.y, wp[2 * i + 1]);
        }
        float dot = f2sum(fadd2(a0, a1));
        float xj = 0.f;
        if ((vm >> k) & 1)
            xj = g_proj[(size_t)ss_[local][k] * 128 + h];  // src half
        m[k] = fmaxf(dot + xj, 0.f) + 1e-7f;
    }

    // thread-local softmax over valid k
    float gmax = -3.4e38f;
#pragma unroll
    for (int k = 0; k < KNB; k++)
        if ((vm >> k) & 1) gmax = fmaxf(gmax, m[k]);

    float den = 1e-16f, num = 0.f;
#pragma unroll
    for (int k = 0; k < KNB; k++)
        if ((vm >> k) & 1) {
            float a = __expf(m[k] - gmax);
            den += a;
            num = fmaf(m[k], a, num);
        }

    if (active) {
        float dstf = g_proj[(size_t)node * 128 + 64 + h];  // dst half
        g_out[(size_t)node * H + h] = num / den + dstf;
    }
}

// =====================================================================
// Kernel C: g_h = g_out @ w1.T  ([N,64] x [128,64] -> [N,128])
// + fused BN partial statistics (per-block column sums / sumsq).
// =====================================================================
__global__ void __launch_bounds__(256)
mlp1_kernel(const float* __restrict__ w1, int n)
{
    __shared__ __align__(16) float xs[64][36];
    __shared__ float rs [16][128];
    __shared__ float rs2[16][128];
    const int t  = threadIdx.x;
    const int tx = t & 15, ty = t >> 4;
    const int n0 = blockIdx.x * 64;

    const float* wbase = w1 + (size_t)(tx * 8) * 64;

    unsigned long long acc2[4][8];
#pragma unroll
    for (int i = 0; i < 4; i++)
#pragma unroll
        for (int j = 0; j < 8; j++) acc2[i][j] = 0ull;

    for (int dt = 0; dt < 64; dt += 32) {
#pragma unroll
        for (int it = 0; it < 2; it++) {
            int idx = t + it * 256;
            int row = idx >> 3, q = idx & 7;
            int gn  = n0 + row;
            float4 v = make_float4(0.f, 0.f, 0.f, 0.f);
            if (gn < n) v = *(const float4*)&g_out[(size_t)gn * H + dt + q * 4];
            *(float4*)&xs[row][q * 4] = v;
        }
        __syncthreads();

#pragma unroll
        for (int dq = 0; dq < 32; dq += 4) {
            ulonglong2 av[4];
#pragma unroll
            for (int i = 0; i < 4; i++)
                av[i] = *(const ulonglong2*)&xs[ty * 4 + i][dq];
#pragma unroll
            for (int j = 0; j < 8; j++) {
                ulonglong2 bv = *(const ulonglong2*)(wbase + (size_t)j * 64 + dt + dq);
#pragma unroll
                for (int i = 0; i < 4; i++) {
                    ffma2(acc2[i][j], av[i].x, bv.x);
                    ffma2(acc2[i][j], av[i].y, bv.y);
                }
            }
        }
        __syncthreads();
    }

    float o[4][8];
#pragma unroll
    for (int i = 0; i < 4; i++)
#pragma unroll
        for (int j = 0; j < 8; j++) o[i][j] = f2sum(acc2[i][j]);

#pragma unroll
    for (int i = 0; i < 4; i++) {
        int gn = n0 + ty * 4 + i;
        if (gn < n) {
            *(float4*)&g_h[(size_t)gn * H2 + tx * 8] =
                make_float4(o[i][0], o[i][1], o[i][2], o[i][3]);
            *(float4*)&g_h[(size_t)gn * H2 + tx * 8 + 4] =
                make_float4(o[i][4], o[i][5], o[i][6], o[i][7]);
        }
    }

    // BN partial stats: per-thread column sums over its 4 nodes.
    // Rows with gn >= n are exactly zero (zero-padded xs) -> contribute nothing.
#pragma unroll
    for (int j = 0; j < 8; j++) {
        float s = 0.f, s2 = 0.f;
#pragma unroll
        for (int i = 0; i < 4; i++) {
            float v = o[i][j];
            // mask padded rows (acc is 0 there already, but be explicit)
            s += v;
            s2 = fmaf(v, v, s2);
        }
        rs [ty][tx * 8 + j] = s;
        rs2[ty][tx * 8 + j] = s2;
    }
    __syncthreads();
    if (t < 128) {
        float s = 0.f, s2 = 0.f;
#pragma unroll
        for (int r = 0; r < 16; r++) { s += rs[r][t]; s2 += rs2[r][t]; }
        g_part[(size_t)blockIdx.x * H2 + t]              = s;
        g_part[(size_t)NBMAX * H2 + (size_t)blockIdx.x * H2 + t] = s2;
    }
}

// Kernel D: fold partials -> BN scale/bias
__global__ void __launch_bounds__(128)
fstats_kernel(const float* __restrict__ gamma, const float* __restrict__ beta,
              int n, int nb)
{
    const int c = threadIdx.x;
    float s = 0.f, s2 = 0.f;
    for (int b = 0; b < nb; b++) {
        s  += g_part[(size_t)b * H2 + c];
        s2 += g_part[(size_t)NBMAX * H2 + (size_t)b * H2 + c];
    }
    float inv_n = 1.f / (float)n;
    float mean  = s * inv_n;
    float var   = s2 * inv_n - mean * mean;
    float sc    = gamma[c] * rsqrtf(var + 1e-5f);
    g_sb[c]      = sc;
    g_sb[H2 + c] = beta[c] - mean * sc;
}

// =====================================================================
// Kernel E: out = relu(bn(g_h)) @ w2.T  ([N,128] x [64,128] -> [N,64])
// BN affine + relu applied during staging; f32x2 d-packed inner loop.
// =====================================================================
__global__ void __launch_bounds__(256)
mlp2_kernel(const float* __restrict__ w2, float* __restrict__ outp, int n)
{
    __shared__ __align__(16) float hs[64][36];
    const int t  = threadIdx.x;
    const int tx = t & 15, ty = t >> 4;
    const int n0 = blockIdx.x * 64;

    const float* wbase = w2 + (size_t)(tx * 4) * 128;

    unsigned long long acc2[4][4];
#pragma unroll
    for (int i = 0; i < 4; i++)
#pragma unroll
        for (int j = 0; j < 4; j++) acc2[i][j] = 0ull;

    for (int dt = 0; dt < 128; dt += 32) {
#pragma unroll
        for (int it = 0; it < 2; it++) {
            int idx = t + it * 256;
            int row = idx >> 3, q = idx & 7;
            int gn  = n0 + row;
            int d   = dt + q * 4;
            float4 v = make_float4(0.f, 0.f, 0.f, 0.f);
            if (gn < n) v = *(const float4*)&g_h[(size_t)gn * H2 + d];
            float4 sc = *(const float4*)&g_sb[d];
            float4 bi = *(const float4*)&g_sb[H2 + d];
            float4 r;
            r.x = fmaxf(fmaf(v.x, sc.x, bi.x), 0.f);
            r.y = fmaxf(fmaf(v.y, sc.y, bi.y), 0.f);
            r.z = fmaxf(fmaf(v.z, sc.z, bi.z), 0.f);
            r.w = fmaxf(fmaf(v.w, sc.w, bi.w), 0.f);
            *(float4*)&hs[row][q * 4] = r;
        }
        __syncthreads();

#pragma unroll
        for (int dq = 0; dq < 32; dq += 4) {
            ulonglong2 av[4];
#pragma unroll
            for (int i = 0; i < 4; i++)
                av[i] = *(const ulonglong2*)&hs[ty * 4 + i][dq];
#pragma unroll
            for (int j = 0; j < 4; j++) {
                ulonglong2 bv = *(const ulonglong2*)(wbase + (size_t)j * 128 + dt + dq);
#pragma unroll
                for (int i = 0; i < 4; i++) {
                    ffma2(acc2[i][j], av[i].x, bv.x);
                    ffma2(acc2[i][j], av[i].y, bv.y);
                }
            }
        }
        __syncthreads();
    }
#pragma unroll
    for (int i = 0; i < 4; i++) {
        int gn = n0 + ty * 4 + i;
        if (gn < n) {
            float o[4];
#pragma unroll
            for (int j = 0; j < 4; j++) o[j] = f2sum(acc2[i][j]);
            *(float4*)&outp[(size_t)gn * H + tx * 4] =
                make_float4(o[0], o[1], o[2], o[3]);
        }
    }
}

// =====================================================================
extern "C" void kernel_launch(void* const* d_in, const int* in_sizes, int n_in,
                              void* d_out, int out_size)
{
    const float* x      = (const float*)d_in[0];
    const float* ea     = (const float*)d_in[1];
    const float* w_src  = (const float*)d_in[2];
    const float* w_dst  = (const float*)d_in[3];
    const float* w_edge = (const float*)d_in[4];
    const float* w1     = (const float*)d_in[5];
    const float* gamma  = (const float*)d_in[6];
    const float* beta   = (const float*)d_in[7];
    const float* w2     = (const float*)d_in[8];
    const int*   ei     = (const int*)d_in[9];   // edge_index [2,E], row0 = src
    const int*   nbr    = (const int*)d_in[10];  // [N,32]
    float* outp = (float*)d_out;

    int n = in_sizes[0] / INC;
    if (n > MAXN) n = MAXN;

    int gb64 = (n + 63) / 64;
    proj_kernel <<<gb64, 256>>>(x, w_src, w_dst, n);
    edge_kernel <<<(n + 1) / 2, 128>>>(ea, w_edge, ei, nbr, n);
    mlp1_kernel <<<gb64, 256>>>(w1, n);
    fstats_kernel<<<1, 128>>>(gamma, beta, n, gb64);
    mlp2_kernel <<<gb64, 256>>>(w2, outp, n);
}

// round 4
// speedup vs baseline: 2.0795x; 2.0795x over previous
#include <cuda_runtime.h>
#include <cuda_bf16.h>
#include <cstdint>

#define MAXN   50000
#define KNB    32
#define INC    128
#define H      64
#define EDGED  32
#define H2     128
#define NBMAX  782   // ceil(MAXN/64)

// ---------------- scratch (static device memory; no allocation) ----------------
__device__ float g_proj[(size_t)MAXN * 128];   // [n][0..63]=x@w_src.T, [64..127]=x@w_dst.T
__device__ float g_out [(size_t)MAXN * H];     // aggregated node features
__device__ float g_h   [(size_t)MAXN * H2];    // MLP hidden
__device__ float g_part[2 * NBMAX * H2];       // BN partial sums / sumsq
__device__ float g_sb  [2 * H2];               // BN scale, bias

// ---------------- helpers ----------------
__device__ __forceinline__ unsigned pack_split_hi(float a, float b,
                                                  unsigned& lo_pack) {
    __nv_bfloat16 ha = __float2bfloat16(a);
    __nv_bfloat16 hb = __float2bfloat16(b);
    float ra = a - __bfloat162float(ha);
    float rb = b - __bfloat162float(hb);
    __nv_bfloat162 L = __halves2bfloat162(__float2bfloat16(ra), __float2bfloat16(rb));
    __nv_bfloat162 Hh = __halves2bfloat162(ha, hb);
    lo_pack = *reinterpret_cast<unsigned*>(&L);
    return *reinterpret_cast<unsigned*>(&Hh);
}

__device__ __forceinline__ void mma_bf16(float& d0, float& d1, float& d2, float& d3,
                                         unsigned a0, unsigned a1, unsigned a2, unsigned a3,
                                         unsigned b0, unsigned b1) {
    asm volatile(
        "mma.sync.aligned.m16n8k16.row.col.f32.bf16.bf16.f32 "
        "{%0,%1,%2,%3}, {%4,%5,%6,%7}, {%8,%9}, {%0,%1,%2,%3};"
        : "+f"(d0), "+f"(d1), "+f"(d2), "+f"(d3)
        : "r"(a0), "r"(a1), "r"(a2), "r"(a3), "r"(b0), "r"(b1));
}

// =====================================================================
// Kernel A: g_proj[n][c] = x[n] . W[c]  (W = [w_src ; w_dst], 128x128)
// (R2-proven scalar version)
// =====================================================================
__global__ void __launch_bounds__(256)
proj_kernel(const float* __restrict__ x,
            const float* __restrict__ w_src,
            const float* __restrict__ w_dst, int n)
{
    __shared__ float xsT[32][64];
    __shared__ float ws [32][128];
    const int t  = threadIdx.x;
    const int tx = t & 15, ty = t >> 4;
    const int n0 = blockIdx.x * 64;

    float acc[4][8];
#pragma unroll
    for (int i = 0; i < 4; i++)
#pragma unroll
        for (int j = 0; j < 8; j++) acc[i][j] = 0.f;

    for (int dt = 0; dt < 128; dt += 32) {
        {
            int r  = t >> 3;
            int dq = (t & 7) * 4;
#pragma unroll
            for (int it = 0; it < 2; it++) {
                int row = r + it * 32;
                int gn  = n0 + row;
                float4 v = make_float4(0.f, 0.f, 0.f, 0.f);
                if (gn < n) v = *(const float4*)&x[(size_t)gn * 128 + dt + dq];
                xsT[dq + 0][row] = v.x; xsT[dq + 1][row] = v.y;
                xsT[dq + 2][row] = v.z; xsT[dq + 3][row] = v.w;
            }
        }
        {
            int c  = t >> 1;
            int dh = (t & 1) * 16;
            const float* wrow = (c < 64) ? (w_src + (size_t)c * 128)
                                         : (w_dst + (size_t)(c - 64) * 128);
#pragma unroll
            for (int q = 0; q < 4; q++) {
                float4 v = *(const float4*)&wrow[dt + dh + q * 4];
                ws[dh + q * 4 + 0][c] = v.x; ws[dh + q * 4 + 1][c] = v.y;
                ws[dh + q * 4 + 2][c] = v.z; ws[dh + q * 4 + 3][c] = v.w;
            }
        }
        __syncthreads();
#pragma unroll
        for (int d = 0; d < 32; d++) {
            float4 av = *(const float4*)&xsT[d][ty * 4];
            float4 b0 = *(const float4*)&ws[d][tx * 8];
            float4 b1 = *(const float4*)&ws[d][tx * 8 + 4];
            float a[4] = {av.x, av.y, av.z, av.w};
            float b[8] = {b0.x, b0.y, b0.z, b0.w, b1.x, b1.y, b1.z, b1.w};
#pragma unroll
            for (int i = 0; i < 4; i++)
#pragma unroll
                for (int j = 0; j < 8; j++)
                    acc[i][j] = fmaf(a[i], b[j], acc[i][j]);
        }
        __syncthreads();
    }
#pragma unroll
    for (int i = 0; i < 4; i++) {
        int gn = n0 + ty * 4 + i;
        if (gn < n) {
            *(float4*)&g_proj[(size_t)gn * 128 + tx * 8] =
                make_float4(acc[i][0], acc[i][1], acc[i][2], acc[i][3]);
            *(float4*)&g_proj[(size_t)gn * 128 + tx * 8 + 4] =
                make_float4(acc[i][4], acc[i][5], acc[i][6], acc[i][7]);
        }
    }
}

// =====================================================================
// Kernel B: per-edge MLP (tensor-core bf16 split) + softmax aggregation
// block = 2 nodes = 64 edges; 128 threads = 4 warps.
// P[64,64] = ea_tile[64,32] @ w_edge.T[32,64] via m16n8k16 bf16 3-pass.
// =====================================================================
__global__ void __launch_bounds__(128)
edge_kernel(const float* __restrict__ ea,
            const float* __restrict__ w_edge,
            const int*   __restrict__ ei,   // edge_index row 0 (src)
            const int*   __restrict__ nbr,
            int n)
{
    __shared__ __align__(16) __nv_bfloat16 eah[64][40];
    __shared__ __align__(16) __nv_bfloat16 eal[64][40];
    __shared__ __align__(16) __nv_bfloat16 wh_s[64][40];
    __shared__ __align__(16) __nv_bfloat16 wl_s[64][40];
    __shared__ float    msg_s[64][66];
    __shared__ int      se_[2][KNB];
    __shared__ int      ss_[2][KNB];
    __shared__ unsigned smask[2];

    const int tid   = threadIdx.x;
    const int node0 = blockIdx.x * 2;

    // ---- setup: neighbor lists, masks ----
    if (tid < 64) {
        int local = tid >> 5, k = tid & 31;
        int node = node0 + local;
        int e = (node < n) ? nbr[(size_t)node * KNB + k] : -1;
        se_[local][k] = e;
        ss_[local][k] = (e >= 0) ? ei[e] : 0;
        unsigned msk = __ballot_sync(0xffffffffu, e >= 0);
        if (k == 0) smask[local] = msk;
    }

    // ---- stage w_edge hi/lo (64 rows x 32) ----
    for (int i = tid; i < 512; i += 128) {
        int r = i >> 3, q = i & 7;
        float4 v = *(const float4*)&w_edge[(size_t)r * EDGED + q * 4];
        unsigned l0, l1, h0, h1;
        h0 = pack_split_hi(v.x, v.y, l0);
        h1 = pack_split_hi(v.z, v.w, l1);
        *(uint2*)&wh_s[r][q * 4] = make_uint2(h0, h1);
        *(uint2*)&wl_s[r][q * 4] = make_uint2(l0, l1);
    }
    __syncthreads();

    // ---- stage gathered edge_attr hi/lo ----
    for (int i = tid; i < 512; i += 128) {
        int r = i >> 3, q = i & 7;
        int local = r >> 5, k = r & 31;
        float4 v = make_float4(0.f, 0.f, 0.f, 0.f);
        if ((smask[local] >> k) & 1)
            v = *(const float4*)&ea[(size_t)se_[local][k] * EDGED + q * 4];
        unsigned l0, l1, h0, h1;
        h0 = pack_split_hi(v.x, v.y, l0);
        h1 = pack_split_hi(v.z, v.w, l1);
        *(uint2*)&eah[r][q * 4] = make_uint2(h0, h1);
        *(uint2*)&eal[r][q * 4] = make_uint2(l0, l1);
    }
    __syncthreads();

    // ---- MMA phase: warp w owns rows [16w, 16w+16) ----
    {
        const int w = tid >> 5, lane = tid & 31;
        const int g = lane >> 2, t4 = lane & 3;
        const int r0 = w * 16 + g, r1 = r0 + 8;

        unsigned ah[2][4], al[2][4];
#pragma unroll
        for (int ks = 0; ks < 2; ks++) {
            int c0 = ks * 16 + 2 * t4;
            ah[ks][0] = *(const unsigned*)&eah[r0][c0];
            ah[ks][1] = *(const unsigned*)&eah[r1][c0];
            ah[ks][2] = *(const unsigned*)&eah[r0][c0 + 8];
            ah[ks][3] = *(const unsigned*)&eah[r1][c0 + 8];
            al[ks][0] = *(const unsigned*)&eal[r0][c0];
            al[ks][1] = *(const unsigned*)&eal[r1][c0];
            al[ks][2] = *(const unsigned*)&eal[r0][c0 + 8];
            al[ks][3] = *(const unsigned*)&eal[r1][c0 + 8];
        }

#pragma unroll
        for (int j = 0; j < 8; j++) {
            float d0 = 0.f, d1 = 0.f, d2 = 0.f, d3 = 0.f;
#pragma unroll
            for (int ks = 0; ks < 2; ks++) {
                int c0 = ks * 16 + 2 * t4;
                int rn = j * 8 + g;
                unsigned bh0 = *(const unsigned*)&wh_s[rn][c0];
                unsigned bh1 = *(const unsigned*)&wh_s[rn][c0 + 8];
                unsigned bl0 = *(const unsigned*)&wl_s[rn][c0];
                unsigned bl1 = *(const unsigned*)&wl_s[rn][c0 + 8];
                mma_bf16(d0, d1, d2, d3, ah[ks][0], ah[ks][1], ah[ks][2], ah[ks][3], bh0, bh1);
                mma_bf16(d0, d1, d2, d3, al[ks][0], al[ks][1], al[ks][2], al[ks][3], bh0, bh1);
                mma_bf16(d0, d1, d2, d3, ah[ks][0], ah[ks][1], ah[ks][2], ah[ks][3], bl0, bl1);
            }
            int c = j * 8 + 2 * t4;
            *(float2*)&msg_s[r0][c] = make_float2(d0, d1);
            *(float2*)&msg_s[r1][c] = make_float2(d2, d3);
        }
    }
    __syncthreads();

    // ---- softmax phase: thread = (node local, channel h) ----
    {
        const int local = tid >> 6;
        const int h     = tid & 63;
        const int node  = node0 + local;
        const unsigned vm = smask[local];

        float m[KNB];
#pragma unroll
        for (int k = 0; k < KNB; k++) {
            float p  = msg_s[local * 32 + k][h];
            float xj = 0.f;
            if ((vm >> k) & 1)
                xj = g_proj[(size_t)ss_[local][k] * 128 + h];  // src half
            m[k] = fmaxf(p + xj, 0.f) + 1e-7f;
        }

        float gmax = -3.4e38f;
#pragma unroll
        for (int k = 0; k < KNB; k++)
            if ((vm >> k) & 1) gmax = fmaxf(gmax, m[k]);

        float den = 1e-16f, num = 0.f;
#pragma unroll
        for (int k = 0; k < KNB; k++)
            if ((vm >> k) & 1) {
                float a = __expf(m[k] - gmax);
                den += a;
                num = fmaf(m[k], a, num);
            }

        if (node < n) {
            float dstf = g_proj[(size_t)node * 128 + 64 + h];  // dst half
            g_out[(size_t)node * H + h] = num / den + dstf;
        }
    }
}

// =====================================================================
// Kernel C: g_h = g_out @ w1.T  ([N,64]x[128,64]->[N,128]) + fused BN stats
// (R2-proven scalar core + partial-stats epilogue)
// =====================================================================
__global__ void __launch_bounds__(256)
mlp1_kernel(const float* __restrict__ w1, int n)
{
    __shared__ float osT[32][64];
    __shared__ float ws [32][128];
    __shared__ float rs [16][128];
    __shared__ float rs2[16][128];
    const int t  = threadIdx.x;
    const int tx = t & 15, ty = t >> 4;
    const int n0 = blockIdx.x * 64;

    float acc[4][8];
#pragma unroll
    for (int i = 0; i < 4; i++)
#pragma unroll
        for (int j = 0; j < 8; j++) acc[i][j] = 0.f;

    for (int dt = 0; dt < 64; dt += 32) {
        {
            int r  = t >> 3;
            int dq = (t & 7) * 4;
#pragma unroll
            for (int it = 0; it < 2; it++) {
                int row = r + it * 32;
                int gn  = n0 + row;
                float4 v = make_float4(0.f, 0.f, 0.f, 0.f);
                if (gn < n) v = *(const float4*)&g_out[(size_t)gn * H + dt + dq];
                osT[dq + 0][row] = v.x; osT[dq + 1][row] = v.y;
                osT[dq + 2][row] = v.z; osT[dq + 3][row] = v.w;
            }
        }
        {
            int c  = t >> 1;
            int dh = (t & 1) * 16;
            const float* wrow = w1 + (size_t)c * 64;
#pragma unroll
            for (int q = 0; q < 4; q++) {
                float4 v = *(const float4*)&wrow[dt + dh + q * 4];
                ws[dh + q * 4 + 0][c] = v.x; ws[dh + q * 4 + 1][c] = v.y;
                ws[dh + q * 4 + 2][c] = v.z; ws[dh + q * 4 + 3][c] = v.w;
            }
        }
        __syncthreads();
#pragma unroll
        for (int d = 0; d < 32; d++) {
            float4 av = *(const float4*)&osT[d][ty * 4];
            float4 b0 = *(const float4*)&ws[d][tx * 8];
            float4 b1 = *(const float4*)&ws[d][tx * 8 + 4];
            float a[4] = {av.x, av.y, av.z, av.w};
            float b[8] = {b0.x, b0.y, b0.z, b0.w, b1.x, b1.y, b1.z, b1.w};
#pragma unroll
            for (int i = 0; i < 4; i++)
#pragma unroll
                for (int j = 0; j < 8; j++)
                    acc[i][j] = fmaf(a[i], b[j], acc[i][j]);
        }
        __syncthreads();
    }
#pragma unroll
    for (int i = 0; i < 4; i++) {
        int gn = n0 + ty * 4 + i;
        if (gn < n) {
            *(float4*)&g_h[(size_t)gn * H2 + tx * 8] =
                make_float4(acc[i][0], acc[i][1], acc[i][2], acc[i][3]);
            *(float4*)&g_h[(size_t)gn * H2 + tx * 8 + 4] =
                make_float4(acc[i][4], acc[i][5], acc[i][6], acc[i][7]);
        }
    }

    // fused BN partial stats (padded rows are exactly zero -> no contribution)
#pragma unroll
    for (int j = 0; j < 8; j++) {
        float s = 0.f, s2 = 0.f;
#pragma unroll
        for (int i = 0; i < 4; i++) {
            float v = acc[i][j];
            s += v;
            s2 = fmaf(v, v, s2);
        }
        rs [ty][tx * 8 + j] = s;
        rs2[ty][tx * 8 + j] = s2;
    }
    __syncthreads();
    if (t < 128) {
        float s = 0.f, s2 = 0.f;
#pragma unroll
        for (int r = 0; r < 16; r++) { s += rs[r][t]; s2 += rs2[r][t]; }
        g_part[(size_t)blockIdx.x * H2 + t]                          = s;
        g_part[(size_t)NBMAX * H2 + (size_t)blockIdx.x * H2 + t]     = s2;
    }
}

// Kernel D: fold partials -> BN scale/bias (parallel over 8 slices/column)
__global__ void __launch_bounds__(1024)
fstats_kernel(const float* __restrict__ gamma, const float* __restrict__ beta,
              int n, int nb)
{
    __shared__ float sh[8][128], sh2[8][128];
    const int c  = threadIdx.x & 127;
    const int s8 = threadIdx.x >> 7;
    float s = 0.f, s2 = 0.f;
    for (int b = s8; b < nb; b += 8) {
        s  += g_part[(size_t)b * H2 + c];
        s2 += g_part[(size_t)NBMAX * H2 + (size_t)b * H2 + c];
    }
    sh[s8][c] = s; sh2[s8][c] = s2;
    __syncthreads();
    if (threadIdx.x < 128) {
        s = 0.f; s2 = 0.f;
#pragma unroll
        for (int r = 0; r < 8; r++) { s += sh[r][c]; s2 += sh2[r][c]; }
        float inv_n = 1.f / (float)n;
        float mean  = s * inv_n;
        float var   = s2 * inv_n - mean * mean;
        float sc    = gamma[c] * rsqrtf(var + 1e-5f);
        g_sb[c]      = sc;
        g_sb[H2 + c] = beta[c] - mean * sc;
    }
}

// =====================================================================
// Kernel E: out = relu(bn(g_h)) @ w2.T  ([N,128]x[64,128]->[N,64])
// (R2-proven scalar version)
// =====================================================================
__global__ void __launch_bounds__(256)
mlp2_kernel(const float* __restrict__ w2, float* __restrict__ outp, int n)
{
    __shared__ float hsT[32][64];
    __shared__ float ws [32][64];
    const int t  = threadIdx.x;
    const int tx = t & 15, ty = t >> 4;
    const int n0 = blockIdx.x * 64;

    float acc[4][4];
#pragma unroll
    for (int i = 0; i < 4; i++)
#pragma unroll
        for (int j = 0; j < 4; j++) acc[i][j] = 0.f;

    for (int dt = 0; dt < 128; dt += 32) {
        {
            int r  = t >> 3;
            int dq = (t & 7) * 4;
#pragma unroll
            for (int it = 0; it < 2; it++) {
                int row = r + it * 32;
                int gn  = n0 + row;
                float4 v = make_float4(0.f, 0.f, 0.f, 0.f);
                if (gn < n) v = *(const float4*)&g_h[(size_t)gn * H2 + dt + dq];
                float sc0 = g_sb[dt + dq + 0], bi0 = g_sb[H2 + dt + dq + 0];
                float sc1 = g_sb[dt + dq + 1], bi1 = g_sb[H2 + dt + dq + 1];
                float sc2 = g_sb[dt + dq + 2], bi2 = g_sb[H2 + dt + dq + 2];
                float sc3 = g_sb[dt + dq + 3], bi3 = g_sb[H2 + dt + dq + 3];
                hsT[dq + 0][row] = fmaxf(fmaf(v.x, sc0, bi0), 0.f);
                hsT[dq + 1][row] = fmaxf(fmaf(v.y, sc1, bi1), 0.f);
                hsT[dq + 2][row] = fmaxf(fmaf(v.z, sc2, bi2), 0.f);
                hsT[dq + 3][row] = fmaxf(fmaf(v.w, sc3, bi3), 0.f);
            }
        }
        {
            int c  = t >> 2;
            int dq = (t & 3) * 8;
            const float* wrow = w2 + (size_t)c * 128;
#pragma unroll
            for (int q = 0; q < 2; q++) {
                float4 v = *(const float4*)&wrow[dt + dq + q * 4];
                ws[dq + q * 4 + 0][c] = v.x; ws[dq + q * 4 + 1][c] = v.y;
                ws[dq + q * 4 + 2][c] = v.z; ws[dq + q * 4 + 3][c] = v.w;
            }
        }
        __syncthreads();
#pragma unroll
        for (int d = 0; d < 32; d++) {
            float4 av = *(const float4*)&hsT[d][ty * 4];
            float4 bv = *(const float4*)&ws[d][tx * 4];
            float a[4] = {av.x, av.y, av.z, av.w};
            float b[4] = {bv.x, bv.y, bv.z, bv.w};
#pragma unroll
            for (int i = 0; i < 4; i++)
#pragma unroll
                for (int j = 0; j < 4; j++)
                    acc[i][j] = fmaf(a[i], b[j], acc[i][j]);
        }
        __syncthreads();
    }
#pragma unroll
    for (int i = 0; i < 4; i++) {
        int gn = n0 + ty * 4 + i;
        if (gn < n)
            *(float4*)&outp[(size_t)gn * H + tx * 4] =
                make_float4(acc[i][0], acc[i][1], acc[i][2], acc[i][3]);
    }
}

// =====================================================================
extern "C" void kernel_launch(void* const* d_in, const int* in_sizes, int n_in,
                              void* d_out, int out_size)
{
    const float* x      = (const float*)d_in[0];
    const float* ea     = (const float*)d_in[1];
    const float* w_src  = (const float*)d_in[2];
    const float* w_dst  = (const float*)d_in[3];
    const float* w_edge = (const float*)d_in[4];
    const float* w1     = (const float*)d_in[5];
    const float* gamma  = (const float*)d_in[6];
    const float* beta   = (const float*)d_in[7];
    const float* w2     = (const float*)d_in[8];
    const int*   ei     = (const int*)d_in[9];   // edge_index [2,E], row0 = src
    const int*   nbr    = (const int*)d_in[10];  // [N,32]
    float* outp = (float*)d_out;

    int n = in_sizes[0] / INC;
    if (n > MAXN) n = MAXN;

    int gb64 = (n + 63) / 64;
    proj_kernel <<<gb64, 256>>>(x, w_src, w_dst, n);
    edge_kernel <<<(n + 1) / 2, 128>>>(ea, w_edge, ei, nbr, n);
    mlp1_kernel <<<gb64, 256>>>(w1, n);
    fstats_kernel<<<1, 1024>>>(gamma, beta, n, gb64);
    mlp2_kernel <<<gb64, 256>>>(w2, outp, n);
}

// round 5
// speedup vs baseline: 2.6860x; 1.2917x over previous
#include <cuda_runtime.h>
#include <cuda_bf16.h>
#include <cstdint>

#define MAXN   50000
#define KNB    32
#define INC    128
#define H      64
#define EDGED  32
#define H2     128
#define NBMAX  782   // ceil(MAXN/64)

// ---------------- scratch (static device memory; no allocation) ----------------
__device__ float g_proj[(size_t)MAXN * 128];
__device__ float g_out [(size_t)MAXN * H];
__device__ float g_h   [(size_t)MAXN * H2];
__device__ float g_part [2 * NBMAX * H2];
__device__ float g_part2[2 * 64 * H2];
__device__ float g_sb  [2 * H2];

// Prepacked B fragments (bf16 hi/lo split, MMA register layout):
// uint4 = {bh0, bh1, bl0, bl1} per lane.
__device__ uint4 g_bfrag_proj[8 * 16 * 32];   // [k16][jb(16)][lane]
__device__ uint4 g_bfrag_mlp2[8 * 8 * 32];    // [k16][jb(8)][lane]
__device__ uint4 g_bfrag_edge[2 * 8 * 32];    // [ks][j(8)][lane]

// ---------------- helpers ----------------
__device__ __forceinline__ unsigned pack_split_hi(float a, float b,
                                                  unsigned& lo_pack) {
    __nv_bfloat16 ha = __float2bfloat16(a);
    __nv_bfloat16 hb = __float2bfloat16(b);
    float ra = a - __bfloat162float(ha);
    float rb = b - __bfloat162float(hb);
    __nv_bfloat162 L = __halves2bfloat162(__float2bfloat16(ra), __float2bfloat16(rb));
    __nv_bfloat162 Hh = __halves2bfloat162(ha, hb);
    lo_pack = *reinterpret_cast<unsigned*>(&L);
    return *reinterpret_cast<unsigned*>(&Hh);
}

__device__ __forceinline__ void mma_bf16(float& d0, float& d1, float& d2, float& d3,
                                         unsigned a0, unsigned a1, unsigned a2, unsigned a3,
                                         unsigned b0, unsigned b1) {
    asm volatile(
        "mma.sync.aligned.m16n8k16.row.col.f32.bf16.bf16.f32 "
        "{%0,%1,%2,%3}, {%4,%5,%6,%7}, {%8,%9}, {%0,%1,%2,%3};"
        : "+f"(d0), "+f"(d1), "+f"(d2), "+f"(d3)
        : "r"(a0), "r"(a1), "r"(a2), "r"(a3), "r"(b0), "r"(b1));
}

// =====================================================================
// Kernel P: prepack B fragments (hi/lo split) for proj / mlp2 / edge.
// =====================================================================
__global__ void __launch_bounds__(256)
prep_kernel(const float* __restrict__ w_src,
            const float* __restrict__ w_dst,
            const float* __restrict__ w_edge,
            const float* __restrict__ w2)
{
    int t = blockIdx.x * 256 + threadIdx.x;
    const float* brow;
    int k, idx;
    uint4* dst;
    if (t < 4096) {                 // proj: W=[w_src;w_dst], 128 out x 128 K
        int lane = t & 31, jb = (t >> 5) & 15, k16 = t >> 9;
        int g = lane >> 2, t4 = lane & 3;
        int nn = jb * 8 + g;
        k = k16 * 16 + 2 * t4;
        brow = (nn < 64) ? (w_src + (size_t)nn * 128) : (w_dst + (size_t)(nn - 64) * 128);
        dst = g_bfrag_proj; idx = t;
    } else if (t < 6144) {          // mlp2: w2, 64 out x 128 K
        int u = t - 4096;
        int lane = u & 31, jb = (u >> 5) & 7, k16 = u >> 8;
        int g = lane >> 2, t4 = lane & 3;
        int nn = jb * 8 + g;
        k = k16 * 16 + 2 * t4;
        brow = w2 + (size_t)nn * 128;
        dst = g_bfrag_mlp2; idx = u;
    } else if (t < 6656) {          // edge: w_edge, 64 out x 32 K
        int u = t - 6144;
        int lane = u & 31, j = (u >> 5) & 7, ks = u >> 8;
        int g = lane >> 2, t4 = lane & 3;
        int nn = j * 8 + g;
        k = ks * 16 + 2 * t4;
        brow = w_edge + (size_t)nn * 32;
        dst = g_bfrag_edge; idx = u;
    } else return;

    float v0 = brow[k], v1 = brow[k + 1], v8 = brow[k + 8], v9 = brow[k + 9];
    unsigned l0, l1;
    unsigned h0 = pack_split_hi(v0, v1, l0);
    unsigned h1 = pack_split_hi(v8, v9, l1);
    dst[idx] = make_uint4(h0, h1, l0, l1);
}

// =====================================================================
// Kernel A: proj via tensor MMA. tile 128 nodes x 128 ch, 8 warps (4 rb x 2 cb).
// =====================================================================
__global__ void __launch_bounds__(256)
proj_kernel(const float* __restrict__ x, int n)
{
    __shared__ __align__(16) __nv_bfloat16 ash[128][40];
    __shared__ __align__(16) __nv_bfloat16 asl[128][40];
    const int tid = threadIdx.x;
    const int warp = tid >> 5, lane = tid & 31;
    const int rb = warp >> 1, cb = warp & 1;
    const int g = lane >> 2, t4 = lane & 3;
    const int n0 = blockIdx.x * 128;

    float acc[2][8][4];
#pragma unroll
    for (int mf = 0; mf < 2; mf++)
#pragma unroll
        for (int j = 0; j < 8; j++)
#pragma unroll
            for (int q = 0; q < 4; q++) acc[mf][j][q] = 0.f;

    for (int dt = 0; dt < 128; dt += 32) {
#pragma unroll
        for (int it = 0; it < 4; it++) {
            int i = tid + it * 256;
            int row = i >> 3, q = i & 7;
            int gn = n0 + row;
            float4 v = make_float4(0.f, 0.f, 0.f, 0.f);
            if (gn < n) v = *(const float4*)&x[(size_t)gn * 128 + dt + q * 4];
            unsigned l0, l1;
            unsigned h0 = pack_split_hi(v.x, v.y, l0);
            unsigned h1 = pack_split_hi(v.z, v.w, l1);
            *(uint2*)&ash[row][q * 4] = make_uint2(h0, h1);
            *(uint2*)&asl[row][q * 4] = make_uint2(l0, l1);
        }
        __syncthreads();

#pragma unroll
        for (int ks = 0; ks < 2; ks++) {
            int k16 = (dt >> 4) + ks;
            int c0 = ks * 16 + 2 * t4;
            unsigned ah[2][4], al[2][4];
#pragma unroll
            for (int mf = 0; mf < 2; mf++) {
                int r0 = rb * 32 + mf * 16 + g;
                ah[mf][0] = *(const unsigned*)&ash[r0][c0];
                ah[mf][1] = *(const unsigned*)&ash[r0 + 8][c0];
                ah[mf][2] = *(const unsigned*)&ash[r0][c0 + 8];
                ah[mf][3] = *(const unsigned*)&ash[r0 + 8][c0 + 8];
                al[mf][0] = *(const unsigned*)&asl[r0][c0];
                al[mf][1] = *(const unsigned*)&asl[r0 + 8][c0];
                al[mf][2] = *(const unsigned*)&asl[r0][c0 + 8];
                al[mf][3] = *(const unsigned*)&asl[r0 + 8][c0 + 8];
            }
#pragma unroll
            for (int j = 0; j < 8; j++) {
                uint4 B = g_bfrag_proj[(size_t)(k16 * 16 + cb * 8 + j) * 32 + lane];
#pragma unroll
                for (int mf = 0; mf < 2; mf++) {
                    float* d = acc[mf][j];
                    mma_bf16(d[0], d[1], d[2], d[3], ah[mf][0], ah[mf][1], ah[mf][2], ah[mf][3], B.x, B.y);
                    mma_bf16(d[0], d[1], d[2], d[3], al[mf][0], al[mf][1], al[mf][2], al[mf][3], B.x, B.y);
                    mma_bf16(d[0], d[1], d[2], d[3], ah[mf][0], ah[mf][1], ah[mf][2], ah[mf][3], B.z, B.w);
                }
            }
        }
        __syncthreads();
    }

#pragma unroll
    for (int mf = 0; mf < 2; mf++) {
        int r = n0 + rb * 32 + mf * 16 + g;
#pragma unroll
        for (int j = 0; j < 8; j++) {
            int c = cb * 64 + j * 8 + 2 * t4;
            float* d = acc[mf][j];
            if (r < n)     *(float2*)&g_proj[(size_t)r * 128 + c]       = make_float2(d[0], d[1]);
            if (r + 8 < n) *(float2*)&g_proj[(size_t)(r + 8) * 128 + c] = make_float2(d[2], d[3]);
        }
    }
}

// =====================================================================
// Kernel B: edge MLP (tensor MMA) + softmax aggregation. 4 nodes/block.
// =====================================================================
__global__ void __launch_bounds__(256)
edge_kernel(const float* __restrict__ ea,
            const int*   __restrict__ ei,
            const int*   __restrict__ nbr,
            int n)
{
    __shared__ union {
        struct { __nv_bfloat16 eah[128][40]; __nv_bfloat16 eal[128][40]; } a;
        float msg[128][68];
    } su;
    __shared__ int      se_[4][KNB];
    __shared__ int      ss_[4][KNB];
    __shared__ unsigned smask[4];

    const int tid   = threadIdx.x;
    const int node0 = blockIdx.x * 4;

    if (tid < 128) {
        int local = tid >> 5, k = tid & 31;
        int node = node0 + local;
        int e = (node < n) ? nbr[(size_t)node * KNB + k] : -1;
        se_[local][k] = e;
        ss_[local][k] = (e >= 0) ? ei[e] : 0;
        unsigned msk = __ballot_sync(0xffffffffu, e >= 0);
        if (k == 0) smask[local] = msk;
    }
    __syncthreads();

    // stage gathered edge_attr hi/lo (128 rows x 32)
#pragma unroll
    for (int it = 0; it < 4; it++) {
        int i = tid + it * 256;
        int row = i >> 3, q = i & 7;
        int local = row >> 5, k = row & 31;
        float4 v = make_float4(0.f, 0.f, 0.f, 0.f);
        if ((smask[local] >> k) & 1)
            v = *(const float4*)&ea[(size_t)se_[local][k] * EDGED + q * 4];
        unsigned l0, l1;
        unsigned h0 = pack_split_hi(v.x, v.y, l0);
        unsigned h1 = pack_split_hi(v.z, v.w, l1);
        *(uint2*)&su.a.eah[row][q * 4] = make_uint2(h0, h1);
        *(uint2*)&su.a.eal[row][q * 4] = make_uint2(l0, l1);
    }
    __syncthreads();

    // load A frags (both k16 chunks) into registers, then free the tile
    const int w8 = tid >> 5, lane = tid & 31;
    const int g = lane >> 2, t4 = lane & 3;
    unsigned ah[2][4], al[2][4];
    {
        const int r0 = w8 * 16 + g, r1 = r0 + 8;
#pragma unroll
        for (int ks = 0; ks < 2; ks++) {
            int c0 = ks * 16 + 2 * t4;
            ah[ks][0] = *(const unsigned*)&su.a.eah[r0][c0];
            ah[ks][1] = *(const unsigned*)&su.a.eah[r1][c0];
            ah[ks][2] = *(const unsigned*)&su.a.eah[r0][c0 + 8];
            ah[ks][3] = *(const unsigned*)&su.a.eah[r1][c0 + 8];
            al[ks][0] = *(const unsigned*)&su.a.eal[r0][c0];
            al[ks][1] = *(const unsigned*)&su.a.eal[r1][c0];
            al[ks][2] = *(const unsigned*)&su.a.eal[r0][c0 + 8];
            al[ks][3] = *(const unsigned*)&su.a.eal[r1][c0 + 8];
        }
    }
    __syncthreads();   // tile now dead; msg may overwrite

    {
        const int r0 = w8 * 16 + g, r1 = r0 + 8;
#pragma unroll
        for (int j = 0; j < 8; j++) {
            float d0 = 0.f, d1 = 0.f, d2 = 0.f, d3 = 0.f;
#pragma unroll
            for (int ks = 0; ks < 2; ks++) {
                uint4 B = g_bfrag_edge[(size_t)(ks * 8 + j) * 32 + lane];
                mma_bf16(d0, d1, d2, d3, ah[ks][0], ah[ks][1], ah[ks][2], ah[ks][3], B.x, B.y);
                mma_bf16(d0, d1, d2, d3, al[ks][0], al[ks][1], al[ks][2], al[ks][3], B.x, B.y);
                mma_bf16(d0, d1, d2, d3, ah[ks][0], ah[ks][1], ah[ks][2], ah[ks][3], B.z, B.w);
            }
            int c = j * 8 + 2 * t4;
            *(float2*)&su.msg[r0][c] = make_float2(d0, d1);
            *(float2*)&su.msg[r1][c] = make_float2(d2, d3);
        }
    }
    __syncthreads();

    // softmax phase: thread = (local node, channel h)
    {
        const int local = tid >> 6;
        const int h     = tid & 63;
        const int node  = node0 + local;
        const unsigned vm = smask[local];

        float m[KNB];
#pragma unroll
        for (int k = 0; k < KNB; k++) {
            float p  = su.msg[local * 32 + k][h];
            float xj = 0.f;
            if ((vm >> k) & 1)
                xj = g_proj[(size_t)ss_[local][k] * 128 + h];
            m[k] = fmaxf(p + xj, 0.f) + 1e-7f;
        }

        float gmax = -3.4e38f;
#pragma unroll
        for (int k = 0; k < KNB; k++)
            if ((vm >> k) & 1) gmax = fmaxf(gmax, m[k]);

        float den = 1e-16f, num = 0.f;
#pragma unroll
        for (int k = 0; k < KNB; k++)
            if ((vm >> k) & 1) {
                float a = __expf(m[k] - gmax);
                den += a;
                num = fmaf(m[k], a, num);
            }

        if (node < n) {
            float dstf = g_proj[(size_t)node * 128 + 64 + h];
            g_out[(size_t)node * H + h] = num / den + dstf;
        }
    }
}

// =====================================================================
// Kernel C: g_h = g_out @ w1.T (scalar, R4-proven) + fused BN stats
// =====================================================================
__global__ void __launch_bounds__(256)
mlp1_kernel(const float* __restrict__ w1, int n)
{
    __shared__ float osT[32][64];
    __shared__ float ws [32][128];
    __shared__ float rs [16][128];
    __shared__ float rs2[16][128];
    const int t  = threadIdx.x;
    const int tx = t & 15, ty = t >> 4;
    const int n0 = blockIdx.x * 64;

    float acc[4][8];
#pragma unroll
    for (int i = 0; i < 4; i++)
#pragma unroll
        for (int j = 0; j < 8; j++) acc[i][j] = 0.f;

    for (int dt = 0; dt < 64; dt += 32) {
        {
            int r  = t >> 3;
            int dq = (t & 7) * 4;
#pragma unroll
            for (int it = 0; it < 2; it++) {
                int row = r + it * 32;
                int gn  = n0 + row;
                float4 v = make_float4(0.f, 0.f, 0.f, 0.f);
                if (gn < n) v = *(const float4*)&g_out[(size_t)gn * H + dt + dq];
                osT[dq + 0][row] = v.x; osT[dq + 1][row] = v.y;
                osT[dq + 2][row] = v.z; osT[dq + 3][row] = v.w;
            }
        }
        {
            int c  = t >> 1;
            int dh = (t & 1) * 16;
            const float* wrow = w1 + (size_t)c * 64;
#pragma unroll
            for (int q = 0; q < 4; q++) {
                float4 v = *(const float4*)&wrow[dt + dh + q * 4];
                ws[dh + q * 4 + 0][c] = v.x; ws[dh + q * 4 + 1][c] = v.y;
                ws[dh + q * 4 + 2][c] = v.z; ws[dh + q * 4 + 3][c] = v.w;
            }
        }
        __syncthreads();
#pragma unroll
        for (int d = 0; d < 32; d++) {
            float4 av = *(const float4*)&osT[d][ty * 4];
            float4 b0 = *(const float4*)&ws[d][tx * 8];
            float4 b1 = *(const float4*)&ws[d][tx * 8 + 4];
            float a[4] = {av.x, av.y, av.z, av.w};
            float b[8] = {b0.x, b0.y, b0.z, b0.w, b1.x, b1.y, b1.z, b1.w};
#pragma unroll
            for (int i = 0; i < 4; i++)
#pragma unroll
                for (int j = 0; j < 8; j++)
                    acc[i][j] = fmaf(a[i], b[j], acc[i][j]);
        }
        __syncthreads();
    }
#pragma unroll
    for (int i = 0; i < 4; i++) {
        int gn = n0 + ty * 4 + i;
        if (gn < n) {
            *(float4*)&g_h[(size_t)gn * H2 + tx * 8] =
                make_float4(acc[i][0], acc[i][1], acc[i][2], acc[i][3]);
            *(float4*)&g_h[(size_t)gn * H2 + tx * 8 + 4] =
                make_float4(acc[i][4], acc[i][5], acc[i][6], acc[i][7]);
        }
    }

#pragma unroll
    for (int j = 0; j < 8; j++) {
        float s = 0.f, s2 = 0.f;
#pragma unroll
        for (int i = 0; i < 4; i++) {
            float v = acc[i][j];
            s += v;
            s2 = fmaf(v, v, s2);
        }
        rs [ty][tx * 8 + j] = s;
        rs2[ty][tx * 8 + j] = s2;
    }
    __syncthreads();
    if (t < 128) {
        float s = 0.f, s2 = 0.f;
#pragma unroll
        for (int r = 0; r < 16; r++) { s += rs[r][t]; s2 += rs2[r][t]; }
        g_part[(size_t)blockIdx.x * H2 + t]                      = s;
        g_part[(size_t)NBMAX * H2 + (size_t)blockIdx.x * H2 + t] = s2;
    }
}

// Kernel D1: fold 782 partials -> 64 (parallel across 64 blocks)
__global__ void __launch_bounds__(128)
fold1_kernel(int nb)
{
    const int c = threadIdx.x;
    const int b = blockIdx.x;
    float s = 0.f, s2 = 0.f;
    for (int r = b; r < nb; r += 64) {
        s  += g_part[(size_t)r * H2 + c];
        s2 += g_part[(size_t)NBMAX * H2 + (size_t)r * H2 + c];
    }
    g_part2[b * H2 + c]            = s;
    g_part2[64 * H2 + b * H2 + c]  = s2;
}

// Kernel D2: fold 64 -> BN scale/bias
__global__ void __launch_bounds__(1024)
fstats_kernel(const float* __restrict__ gamma, const float* __restrict__ beta, int n)
{
    __shared__ float sh[8][128], sh2[8][128];
    const int c  = threadIdx.x & 127;
    const int s8 = threadIdx.x >> 7;
    float s = 0.f, s2 = 0.f;
#pragma unroll
    for (int b = s8; b < 64; b += 8) {
        s  += g_part2[b * H2 + c];
        s2 += g_part2[64 * H2 + b * H2 + c];
    }
    sh[s8][c] = s; sh2[s8][c] = s2;
    __syncthreads();
    if (threadIdx.x < 128) {
        s = 0.f; s2 = 0.f;
#pragma unroll
        for (int r = 0; r < 8; r++) { s += sh[r][c]; s2 += sh2[r][c]; }
        float inv_n = 1.f / (float)n;
        float mean  = s * inv_n;
        float var   = s2 * inv_n - mean * mean;
        float sc    = gamma[c] * rsqrtf(var + 1e-5f);
        g_sb[c]      = sc;
        g_sb[H2 + c] = beta[c] - mean * sc;
    }
}

// =====================================================================
// Kernel E: out = relu(bn(g_h)) @ w2.T via tensor MMA. tile 128 x 64.
// =====================================================================
__global__ void __launch_bounds__(256)
mlp2_kernel(float* __restrict__ outp, int n)
{
    __shared__ __align__(16) __nv_bfloat16 ash[128][40];
    __shared__ __align__(16) __nv_bfloat16 asl[128][40];
    const int tid = threadIdx.x;
    const int warp = tid >> 5, lane = tid & 31;
    const int rb = warp >> 1, cb = warp & 1;
    const int g = lane >> 2, t4 = lane & 3;
    const int n0 = blockIdx.x * 128;

    float acc[2][4][4];
#pragma unroll
    for (int mf = 0; mf < 2; mf++)
#pragma unroll
        for (int j = 0; j < 4; j++)
#pragma unroll
            for (int q = 0; q < 4; q++) acc[mf][j][q] = 0.f;

    for (int dt = 0; dt < 128; dt += 32) {
#pragma unroll
        for (int it = 0; it < 4; it++) {
            int i = tid + it * 256;
            int row = i >> 3, q = i & 7;
            int gn = n0 + row;
            int d  = dt + q * 4;
            float4 v = make_float4(0.f, 0.f, 0.f, 0.f);
            if (gn < n) v = *(const float4*)&g_h[(size_t)gn * H2 + d];
            float4 sc = *(const float4*)&g_sb[d];
            float4 bi = *(const float4*)&g_sb[H2 + d];
            float r0 = fmaxf(fmaf(v.x, sc.x, bi.x), 0.f);
            float r1 = fmaxf(fmaf(v.y, sc.y, bi.y), 0.f);
            float r2 = fmaxf(fmaf(v.z, sc.z, bi.z), 0.f);
            float r3 = fmaxf(fmaf(v.w, sc.w, bi.w), 0.f);
            unsigned l0, l1;
            unsigned h0 = pack_split_hi(r0, r1, l0);
            unsigned h1 = pack_split_hi(r2, r3, l1);
            *(uint2*)&ash[row][q * 4] = make_uint2(h0, h1);
            *(uint2*)&asl[row][q * 4] = make_uint2(l0, l1);
        }
        __syncthreads();

#pragma unroll
        for (int ks = 0; ks < 2; ks++) {
            int k16 = (dt >> 4) + ks;
            int c0 = ks * 16 + 2 * t4;
            unsigned ah[2][4], al[2][4];
#pragma unroll
            for (int mf = 0; mf < 2; mf++) {
                int r0 = rb * 32 + mf * 16 + g;
                ah[mf][0] = *(const unsigned*)&ash[r0][c0];
                ah[mf][1] = *(const unsigned*)&ash[r0 + 8][c0];
                ah[mf][2] = *(const unsigned*)&ash[r0][c0 + 8];
                ah[mf][3] = *(const unsigned*)&ash[r0 + 8][c0 + 8];
                al[mf][0] = *(const unsigned*)&asl[r0][c0];
                al[mf][1] = *(const unsigned*)&asl[r0 + 8][c0];
                al[mf][2] = *(const unsigned*)&asl[r0][c0 + 8];
                al[mf][3] = *(const unsigned*)&asl[r0 + 8][c0 + 8];
            }
#pragma unroll
            for (int j = 0; j < 4; j++) {
                uint4 B = g_bfrag_mlp2[(size_t)(k16 * 8 + cb * 4 + j) * 32 + lane];
#pragma unroll
                for (int mf = 0; mf < 2; mf++) {
                    float* d = acc[mf][j];
                    mma_bf16(d[0], d[1], d[2], d[3], ah[mf][0], ah[mf][1], ah[mf][2], ah[mf][3], B.x, B.y);
                    mma_bf16(d[0], d[1], d[2], d[3], al[mf][0], al[mf][1], al[mf][2], al[mf][3], B.x, B.y);
                    mma_bf16(d[0], d[1], d[2], d[3], ah[mf][0], ah[mf][1], ah[mf][2], ah[mf][3], B.z, B.w);
                }
            }
        }
        __syncthreads();
    }

#pragma unroll
    for (int mf = 0; mf < 2; mf++) {
        int r = n0 + rb * 32 + mf * 16 + g;
#pragma unroll
        for (int j = 0; j < 4; j++) {
            int c = cb * 32 + j * 8 + 2 * t4;
            float* d = acc[mf][j];
            if (r < n)     *(float2*)&outp[(size_t)r * H + c]       = make_float2(d[0], d[1]);
            if (r + 8 < n) *(float2*)&outp[(size_t)(r + 8) * H + c] = make_float2(d[2], d[3]);
        }
    }
}

// =====================================================================
extern "C" void kernel_launch(void* const* d_in, const int* in_sizes, int n_in,
                              void* d_out, int out_size)
{
    const float* x      = (const float*)d_in[0];
    const float* ea     = (const float*)d_in[1];
    const float* w_src  = (const float*)d_in[2];
    const float* w_dst  = (const float*)d_in[3];
    const float* w_edge = (const float*)d_in[4];
    const float* w1     = (const float*)d_in[5];
    const float* gamma  = (const float*)d_in[6];
    const float* beta   = (const float*)d_in[7];
    const float* w2     = (const float*)d_in[8];
    const int*   ei     = (const int*)d_in[9];
    const int*   nbr    = (const int*)d_in[10];
    float* outp = (float*)d_out;

    int n = in_sizes[0] / INC;
    if (n > MAXN) n = MAXN;

    int gb64  = (n + 63) / 64;
    int gb128 = (n + 127) / 128;
    prep_kernel <<<26, 256>>>(w_src, w_dst, w_edge, w2);
    proj_kernel <<<gb128, 256>>>(x, n);
    edge_kernel <<<(n + 3) / 4, 256>>>(ea, ei, nbr, n);
    mlp1_kernel <<<gb64, 256>>>(w1, n);
    fold1_kernel<<<64, 128>>>(gb64);
    fstats_kernel<<<1, 1024>>>(gamma, beta, n);
    mlp2_kernel <<<gb128, 256>>>(outp, n);
}

// round 6
// speedup vs baseline: 2.9126x; 1.0844x over previous
#include <cuda_runtime.h>
#include <cuda_bf16.h>
#include <cstdint>

#define MAXN   50000
#define KNB    32
#define INC    128
#define H      64
#define EDGED  32
#define H2     128
#define NBMAX  391   // ceil(MAXN/128)

// ---------------- scratch (static device memory; no allocation) ----------------
__device__ float g_proj[(size_t)MAXN * 128];
__device__ float g_out [(size_t)MAXN * H];
__device__ float g_h   [(size_t)MAXN * H2];
__device__ float g_part [2 * NBMAX * H2];
__device__ float g_part2[2 * 64 * H2];
__device__ float g_sb  [2 * H2];

// Prepacked B fragments (bf16 hi/lo split, MMA register layout):
// uint4 = {bh0, bh1, bl0, bl1} per lane.
__device__ uint4 g_bfrag_proj[8 * 16 * 32];   // [k16][jb(16)][lane]
__device__ uint4 g_bfrag_mlp2[8 * 8 * 32];    // [k16][jb(8)][lane]
__device__ uint4 g_bfrag_edge[2 * 8 * 32];    // [ks][j(8)][lane]
__device__ uint4 g_bfrag_mlp1[4 * 16 * 32];   // [k16][jb(16)][lane]

// ---------------- helpers ----------------
__device__ __forceinline__ unsigned pack_split_hi(float a, float b,
                                                  unsigned& lo_pack) {
    __nv_bfloat16 ha = __float2bfloat16(a);
    __nv_bfloat16 hb = __float2bfloat16(b);
    float ra = a - __bfloat162float(ha);
    float rb = b - __bfloat162float(hb);
    __nv_bfloat162 L = __halves2bfloat162(__float2bfloat16(ra), __float2bfloat16(rb));
    __nv_bfloat162 Hh = __halves2bfloat162(ha, hb);
    lo_pack = *reinterpret_cast<unsigned*>(&L);
    return *reinterpret_cast<unsigned*>(&Hh);
}

__device__ __forceinline__ void mma_bf16(float& d0, float& d1, float& d2, float& d3,
                                         unsigned a0, unsigned a1, unsigned a2, unsigned a3,
                                         unsigned b0, unsigned b1) {
    asm volatile(
        "mma.sync.aligned.m16n8k16.row.col.f32.bf16.bf16.f32 "
        "{%0,%1,%2,%3}, {%4,%5,%6,%7}, {%8,%9}, {%0,%1,%2,%3};"
        : "+f"(d0), "+f"(d1), "+f"(d2), "+f"(d3)
        : "r"(a0), "r"(a1), "r"(a2), "r"(a3), "r"(b0), "r"(b1));
}

// =====================================================================
// Kernel P: prepack B fragments (hi/lo split) for proj / mlp2 / edge / mlp1.
// =====================================================================
__global__ void __launch_bounds__(256)
prep_kernel(const float* __restrict__ w_src,
            const float* __restrict__ w_dst,
            const float* __restrict__ w_edge,
            const float* __restrict__ w2,
            const float* __restrict__ w1)
{
    int t = blockIdx.x * 256 + threadIdx.x;
    const float* brow;
    int k, idx;
    uint4* dst;
    if (t < 4096) {                 // proj: W=[w_src;w_dst], 128 out x 128 K
        int lane = t & 31, jb = (t >> 5) & 15, k16 = t >> 9;
        int g = lane >> 2, t4 = lane & 3;
        int nn = jb * 8 + g;
        k = k16 * 16 + 2 * t4;
        brow = (nn < 64) ? (w_src + (size_t)nn * 128) : (w_dst + (size_t)(nn - 64) * 128);
        dst = g_bfrag_proj; idx = t;
    } else if (t < 6144) {          // mlp2: w2, 64 out x 128 K
        int u = t - 4096;
        int lane = u & 31, jb = (u >> 5) & 7, k16 = u >> 8;
        int g = lane >> 2, t4 = lane & 3;
        int nn = jb * 8 + g;
        k = k16 * 16 + 2 * t4;
        brow = w2 + (size_t)nn * 128;
        dst = g_bfrag_mlp2; idx = u;
    } else if (t < 6656) {          // edge: w_edge, 64 out x 32 K
        int u = t - 6144;
        int lane = u & 31, j = (u >> 5) & 7, ks = u >> 8;
        int g = lane >> 2, t4 = lane & 3;
        int nn = j * 8 + g;
        k = ks * 16 + 2 * t4;
        brow = w_edge + (size_t)nn * 32;
        dst = g_bfrag_edge; idx = u;
    } else if (t < 8704) {          // mlp1: w1, 128 out x 64 K
        int u = t - 6656;
        int lane = u & 31, jb = (u >> 5) & 15, k16 = u >> 9;
        int g = lane >> 2, t4 = lane & 3;
        int nn = jb * 8 + g;
        k = k16 * 16 + 2 * t4;
        brow = w1 + (size_t)nn * 64;
        dst = g_bfrag_mlp1; idx = u;
    } else return;

    float v0 = brow[k], v1 = brow[k + 1], v8 = brow[k + 8], v9 = brow[k + 9];
    unsigned l0, l1;
    unsigned h0 = pack_split_hi(v0, v1, l0);
    unsigned h1 = pack_split_hi(v8, v9, l1);
    dst[idx] = make_uint4(h0, h1, l0, l1);
}

// =====================================================================
// Kernel A: proj via tensor MMA. tile 128 nodes x 128 ch, 8 warps (4 rb x 2 cb).
// =====================================================================
__global__ void __launch_bounds__(256)
proj_kernel(const float* __restrict__ x, int n)
{
    __shared__ __align__(16) __nv_bfloat16 ash[128][40];
    __shared__ __align__(16) __nv_bfloat16 asl[128][40];
    const int tid = threadIdx.x;
    const int warp = tid >> 5, lane = tid & 31;
    const int rb = warp >> 1, cb = warp & 1;
    const int g = lane >> 2, t4 = lane & 3;
    const int n0 = blockIdx.x * 128;

    float acc[2][8][4];
#pragma unroll
    for (int mf = 0; mf < 2; mf++)
#pragma unroll
        for (int j = 0; j < 8; j++)
#pragma unroll
            for (int q = 0; q < 4; q++) acc[mf][j][q] = 0.f;

    for (int dt = 0; dt < 128; dt += 32) {
#pragma unroll
        for (int it = 0; it < 4; it++) {
            int i = tid + it * 256;
            int row = i >> 3, q = i & 7;
            int gn = n0 + row;
            float4 v = make_float4(0.f, 0.f, 0.f, 0.f);
            if (gn < n) v = *(const float4*)&x[(size_t)gn * 128 + dt + q * 4];
            unsigned l0, l1;
            unsigned h0 = pack_split_hi(v.x, v.y, l0);
            unsigned h1 = pack_split_hi(v.z, v.w, l1);
            *(uint2*)&ash[row][q * 4] = make_uint2(h0, h1);
            *(uint2*)&asl[row][q * 4] = make_uint2(l0, l1);
        }
        __syncthreads();

#pragma unroll
        for (int ks = 0; ks < 2; ks++) {
            int k16 = (dt >> 4) + ks;
            int c0 = ks * 16 + 2 * t4;
            unsigned ah[2][4], al[2][4];
#pragma unroll
            for (int mf = 0; mf < 2; mf++) {
                int r0 = rb * 32 + mf * 16 + g;
                ah[mf][0] = *(const unsigned*)&ash[r0][c0];
                ah[mf][1] = *(const unsigned*)&ash[r0 + 8][c0];
                ah[mf][2] = *(const unsigned*)&ash[r0][c0 + 8];
                ah[mf][3] = *(const unsigned*)&ash[r0 + 8][c0 + 8];
                al[mf][0] = *(const unsigned*)&asl[r0][c0];
                al[mf][1] = *(const unsigned*)&asl[r0 + 8][c0];
                al[mf][2] = *(const unsigned*)&asl[r0][c0 + 8];
                al[mf][3] = *(const unsigned*)&asl[r0 + 8][c0 + 8];
            }
#pragma unroll
            for (int j = 0; j < 8; j++) {
                uint4 B = g_bfrag_proj[(size_t)(k16 * 16 + cb * 8 + j) * 32 + lane];
#pragma unroll
                for (int mf = 0; mf < 2; mf++) {
                    float* d = acc[mf][j];
                    mma_bf16(d[0], d[1], d[2], d[3], ah[mf][0], ah[mf][1], ah[mf][2], ah[mf][3], B.x, B.y);
                    mma_bf16(d[0], d[1], d[2], d[3], al[mf][0], al[mf][1], al[mf][2], al[mf][3], B.x, B.y);
                    mma_bf16(d[0], d[1], d[2], d[3], ah[mf][0], ah[mf][1], ah[mf][2], ah[mf][3], B.z, B.w);
                }
            }
        }
        __syncthreads();
    }

#pragma unroll
    for (int mf = 0; mf < 2; mf++) {
        int r = n0 + rb * 32 + mf * 16 + g;
#pragma unroll
        for (int j = 0; j < 8; j++) {
            int c = cb * 64 + j * 8 + 2 * t4;
            float* d = acc[mf][j];
            if (r < n)     *(float2*)&g_proj[(size_t)r * 128 + c]       = make_float2(d[0], d[1]);
            if (r + 8 < n) *(float2*)&g_proj[(size_t)(r + 8) * 128 + c] = make_float2(d[2], d[3]);
        }
    }
}

// =====================================================================
// Kernel B: edge MLP (tensor MMA) + softmax aggregation. 4 nodes/block.
// =====================================================================
__global__ void __launch_bounds__(256)
edge_kernel(const float* __restrict__ ea,
            const int*   __restrict__ ei,
            const int*   __restrict__ nbr,
            int n)
{
    __shared__ union {
        struct { __nv_bfloat16 eah[128][40]; __nv_bfloat16 eal[128][40]; } a;
        float msg[128][68];
    } su;
    __shared__ int      se_[4][KNB];
    __shared__ int      ss_[4][KNB];
    __shared__ unsigned smask[4];

    const int tid   = threadIdx.x;
    const int node0 = blockIdx.x * 4;

    if (tid < 128) {
        int local = tid >> 5, k = tid & 31;
        int node = node0 + local;
        int e = (node < n) ? nbr[(size_t)node * KNB + k] : -1;
        se_[local][k] = e;
        ss_[local][k] = (e >= 0) ? ei[e] : 0;
        unsigned msk = __ballot_sync(0xffffffffu, e >= 0);
        if (k == 0) smask[local] = msk;
    }
    __syncthreads();

#pragma unroll
    for (int it = 0; it < 4; it++) {
        int i = tid + it * 256;
        int row = i >> 3, q = i & 7;
        int local = row >> 5, k = row & 31;
        float4 v = make_float4(0.f, 0.f, 0.f, 0.f);
        if ((smask[local] >> k) & 1)
            v = *(const float4*)&ea[(size_t)se_[local][k] * EDGED + q * 4];
        unsigned l0, l1;
        unsigned h0 = pack_split_hi(v.x, v.y, l0);
        unsigned h1 = pack_split_hi(v.z, v.w, l1);
        *(uint2*)&su.a.eah[row][q * 4] = make_uint2(h0, h1);
        *(uint2*)&su.a.eal[row][q * 4] = make_uint2(l0, l1);
    }
    __syncthreads();

    const int w8 = tid >> 5, lane = tid & 31;
    const int g = lane >> 2, t4 = lane & 3;
    unsigned ah[2][4], al[2][4];
    {
        const int r0 = w8 * 16 + g, r1 = r0 + 8;
#pragma unroll
        for (int ks = 0; ks < 2; ks++) {
            int c0 = ks * 16 + 2 * t4;
            ah[ks][0] = *(const unsigned*)&su.a.eah[r0][c0];
            ah[ks][1] = *(const unsigned*)&su.a.eah[r1][c0];
            ah[ks][2] = *(const unsigned*)&su.a.eah[r0][c0 + 8];
            ah[ks][3] = *(const unsigned*)&su.a.eah[r1][c0 + 8];
            al[ks][0] = *(const unsigned*)&su.a.eal[r0][c0];
            al[ks][1] = *(const unsigned*)&su.a.eal[r1][c0];
            al[ks][2] = *(const unsigned*)&su.a.eal[r0][c0 + 8];
            al[ks][3] = *(const unsigned*)&su.a.eal[r1][c0 + 8];
        }
    }
    __syncthreads();

    {
        const int r0 = w8 * 16 + g, r1 = r0 + 8;
#pragma unroll
        for (int j = 0; j < 8; j++) {
            float d0 = 0.f, d1 = 0.f, d2 = 0.f, d3 = 0.f;
#pragma unroll
            for (int ks = 0; ks < 2; ks++) {
                uint4 B = g_bfrag_edge[(size_t)(ks * 8 + j) * 32 + lane];
                mma_bf16(d0, d1, d2, d3, ah[ks][0], ah[ks][1], ah[ks][2], ah[ks][3], B.x, B.y);
                mma_bf16(d0, d1, d2, d3, al[ks][0], al[ks][1], al[ks][2], al[ks][3], B.x, B.y);
                mma_bf16(d0, d1, d2, d3, ah[ks][0], ah[ks][1], ah[ks][2], ah[ks][3], B.z, B.w);
            }
            int c = j * 8 + 2 * t4;
            *(float2*)&su.msg[r0][c] = make_float2(d0, d1);
            *(float2*)&su.msg[r1][c] = make_float2(d2, d3);
        }
    }
    __syncthreads();

    {
        const int local = tid >> 6;
        const int h     = tid & 63;
        const int node  = node0 + local;
        const unsigned vm = smask[local];

        float m[KNB];
#pragma unroll
        for (int k = 0; k < KNB; k++) {
            float p  = su.msg[local * 32 + k][h];
            float xj = 0.f;
            if ((vm >> k) & 1)
                xj = g_proj[(size_t)ss_[local][k] * 128 + h];
            m[k] = fmaxf(p + xj, 0.f) + 1e-7f;
        }

        float gmax = -3.4e38f;
#pragma unroll
        for (int k = 0; k < KNB; k++)
            if ((vm >> k) & 1) gmax = fmaxf(gmax, m[k]);

        float den = 1e-16f, num = 0.f;
#pragma unroll
        for (int k = 0; k < KNB; k++)
            if ((vm >> k) & 1) {
                float a = __expf(m[k] - gmax);
                den += a;
                num = fmaf(m[k], a, num);
            }

        if (node < n) {
            float dstf = g_proj[(size_t)node * 128 + 64 + h];
            g_out[(size_t)node * H + h] = num / den + dstf;
        }
    }
}

// =====================================================================
// Kernel C: g_h = g_out @ w1.T via tensor MMA (tile 128x128, single K stage)
// + fused BN partial stats straight from MMA accumulators.
// =====================================================================
__global__ void __launch_bounds__(256)
mlp1_kernel(int n)
{
    __shared__ __align__(16) __nv_bfloat16 ash[128][72];
    __shared__ __align__(16) __nv_bfloat16 asl[128][72];
    __shared__ float rs [4][128];
    __shared__ float rs2[4][128];
    const int tid = threadIdx.x;
    const int warp = tid >> 5, lane = tid & 31;
    const int rb = warp >> 1, cb = warp & 1;
    const int g = lane >> 2, t4 = lane & 3;
    const int n0 = blockIdx.x * 128;

    // stage full K=64 of A (g_out), hi/lo split
#pragma unroll
    for (int it = 0; it < 8; it++) {
        int i = tid + it * 256;
        int row = i >> 4, q = i & 15;
        int gn = n0 + row;
        float4 v = make_float4(0.f, 0.f, 0.f, 0.f);
        if (gn < n) v = *(const float4*)&g_out[(size_t)gn * H + q * 4];
        unsigned l0, l1;
        unsigned h0 = pack_split_hi(v.x, v.y, l0);
        unsigned h1 = pack_split_hi(v.z, v.w, l1);
        *(uint2*)&ash[row][q * 4] = make_uint2(h0, h1);
        *(uint2*)&asl[row][q * 4] = make_uint2(l0, l1);
    }
    __syncthreads();

    float acc[2][8][4];
#pragma unroll
    for (int mf = 0; mf < 2; mf++)
#pragma unroll
        for (int j = 0; j < 8; j++)
#pragma unroll
            for (int q = 0; q < 4; q++) acc[mf][j][q] = 0.f;

#pragma unroll
    for (int k16 = 0; k16 < 4; k16++) {
        int c0 = k16 * 16 + 2 * t4;
        unsigned ah[2][4], al[2][4];
#pragma unroll
        for (int mf = 0; mf < 2; mf++) {
            int r0 = rb * 32 + mf * 16 + g;
            ah[mf][0] = *(const unsigned*)&ash[r0][c0];
            ah[mf][1] = *(const unsigned*)&ash[r0 + 8][c0];
            ah[mf][2] = *(const unsigned*)&ash[r0][c0 + 8];
            ah[mf][3] = *(const unsigned*)&ash[r0 + 8][c0 + 8];
            al[mf][0] = *(const unsigned*)&asl[r0][c0];
            al[mf][1] = *(const unsigned*)&asl[r0 + 8][c0];
            al[mf][2] = *(const unsigned*)&asl[r0][c0 + 8];
            al[mf][3] = *(const unsigned*)&asl[r0 + 8][c0 + 8];
        }
#pragma unroll
        for (int j = 0; j < 8; j++) {
            uint4 B = g_bfrag_mlp1[(size_t)(k16 * 16 + cb * 8 + j) * 32 + lane];
#pragma unroll
            for (int mf = 0; mf < 2; mf++) {
                float* d = acc[mf][j];
                mma_bf16(d[0], d[1], d[2], d[3], ah[mf][0], ah[mf][1], ah[mf][2], ah[mf][3], B.x, B.y);
                mma_bf16(d[0], d[1], d[2], d[3], al[mf][0], al[mf][1], al[mf][2], al[mf][3], B.x, B.y);
                mma_bf16(d[0], d[1], d[2], d[3], ah[mf][0], ah[mf][1], ah[mf][2], ah[mf][3], B.z, B.w);
            }
        }
    }

    // write g_h
#pragma unroll
    for (int mf = 0; mf < 2; mf++) {
        int r = n0 + rb * 32 + mf * 16 + g;
#pragma unroll
        for (int j = 0; j < 8; j++) {
            int c = cb * 64 + j * 8 + 2 * t4;
            float* d = acc[mf][j];
            if (r < n)     *(float2*)&g_h[(size_t)r * H2 + c]       = make_float2(d[0], d[1]);
            if (r + 8 < n) *(float2*)&g_h[(size_t)(r + 8) * H2 + c] = make_float2(d[2], d[3]);
        }
    }

    // fused BN partial stats from accumulators (padded rows are exact zeros)
#pragma unroll
    for (int j = 0; j < 8; j++) {
        float s0 = 0.f, s1 = 0.f, q0 = 0.f, q1 = 0.f;
#pragma unroll
        for (int mf = 0; mf < 2; mf++) {
            float* d = acc[mf][j];
            s0 += d[0] + d[2];
            s1 += d[1] + d[3];
            q0 += d[0] * d[0] + d[2] * d[2];
            q1 += d[1] * d[1] + d[3] * d[3];
        }
        // reduce over g (lane bits 2..4); t4 (bits 0..1) holds distinct columns
#pragma unroll
        for (int off = 4; off < 32; off <<= 1) {
            s0 += __shfl_xor_sync(0xffffffffu, s0, off);
            s1 += __shfl_xor_sync(0xffffffffu, s1, off);
            q0 += __shfl_xor_sync(0xffffffffu, q0, off);
            q1 += __shfl_xor_sync(0xffffffffu, q1, off);
        }
        if (g == 0) {
            int c = cb * 64 + j * 8 + 2 * t4;
            rs [rb][c]     = s0;
            rs [rb][c + 1] = s1;
            rs2[rb][c]     = q0;
            rs2[rb][c + 1] = q1;
        }
    }
    __syncthreads();
    if (tid < 128) {
        float s  = rs [0][tid] + rs [1][tid] + rs [2][tid] + rs [3][tid];
        float s2 = rs2[0][tid] + rs2[1][tid] + rs2[2][tid] + rs2[3][tid];
        g_part[(size_t)blockIdx.x * H2 + tid]                      = s;
        g_part[(size_t)NBMAX * H2 + (size_t)blockIdx.x * H2 + tid] = s2;
    }
}

// Kernel D1: fold partials -> 64
__global__ void __launch_bounds__(128)
fold1_kernel(int nb)
{
    const int c = threadIdx.x;
    const int b = blockIdx.x;
    float s = 0.f, s2 = 0.f;
    for (int r = b; r < nb; r += 64) {
        s  += g_part[(size_t)r * H2 + c];
        s2 += g_part[(size_t)NBMAX * H2 + (size_t)r * H2 + c];
    }
    g_part2[b * H2 + c]            = s;
    g_part2[64 * H2 + b * H2 + c]  = s2;
}

// Kernel D2: fold 64 -> BN scale/bias
__global__ void __launch_bounds__(1024)
fstats_kernel(const float* __restrict__ gamma, const float* __restrict__ beta, int n)
{
    __shared__ float sh[8][128], sh2[8][128];
    const int c  = threadIdx.x & 127;
    const int s8 = threadIdx.x >> 7;
    float s = 0.f, s2 = 0.f;
#pragma unroll
    for (int b = s8; b < 64; b += 8) {
        s  += g_part2[b * H2 + c];
        s2 += g_part2[64 * H2 + b * H2 + c];
    }
    sh[s8][c] = s; sh2[s8][c] = s2;
    __syncthreads();
    if (threadIdx.x < 128) {
        s = 0.f; s2 = 0.f;
#pragma unroll
        for (int r = 0; r < 8; r++) { s += sh[r][c]; s2 += sh2[r][c]; }
        float inv_n = 1.f / (float)n;
        float mean  = s * inv_n;
        float var   = s2 * inv_n - mean * mean;
        float sc    = gamma[c] * rsqrtf(var + 1e-5f);
        g_sb[c]      = sc;
        g_sb[H2 + c] = beta[c] - mean * sc;
    }
}

// =====================================================================
// Kernel E: out = relu(bn(g_h)) @ w2.T via tensor MMA. tile 128 x 64.
// =====================================================================
__global__ void __launch_bounds__(256)
mlp2_kernel(float* __restrict__ outp, int n)
{
    __shared__ __align__(16) __nv_bfloat16 ash[128][40];
    __shared__ __align__(16) __nv_bfloat16 asl[128][40];
    const int tid = threadIdx.x;
    const int warp = tid >> 5, lane = tid & 31;
    const int rb = warp >> 1, cb = warp & 1;
    const int g = lane >> 2, t4 = lane & 3;
    const int n0 = blockIdx.x * 128;

    float acc[2][4][4];
#pragma unroll
    for (int mf = 0; mf < 2; mf++)
#pragma unroll
        for (int j = 0; j < 4; j++)
#pragma unroll
            for (int q = 0; q < 4; q++) acc[mf][j][q] = 0.f;

    for (int dt = 0; dt < 128; dt += 32) {
#pragma unroll
        for (int it = 0; it < 4; it++) {
            int i = tid + it * 256;
            int row = i >> 3, q = i & 7;
            int gn = n0 + row;
            int d  = dt + q * 4;
            float4 v = make_float4(0.f, 0.f, 0.f, 0.f);
            if (gn < n) v = *(const float4*)&g_h[(size_t)gn * H2 + d];
            float4 sc = *(const float4*)&g_sb[d];
            float4 bi = *(const float4*)&g_sb[H2 + d];
            float r0 = fmaxf(fmaf(v.x, sc.x, bi.x), 0.f);
            float r1 = fmaxf(fmaf(v.y, sc.y, bi.y), 0.f);
            float r2 = fmaxf(fmaf(v.z, sc.z, bi.z), 0.f);
            float r3 = fmaxf(fmaf(v.w, sc.w, bi.w), 0.f);
            unsigned l0, l1;
            unsigned h0 = pack_split_hi(r0, r1, l0);
            unsigned h1 = pack_split_hi(r2, r3, l1);
            *(uint2*)&ash[row][q * 4] = make_uint2(h0, h1);
            *(uint2*)&asl[row][q * 4] = make_uint2(l0, l1);
        }
        __syncthreads();

#pragma unroll
        for (int ks = 0; ks < 2; ks++) {
            int k16 = (dt >> 4) + ks;
            int c0 = ks * 16 + 2 * t4;
            unsigned ah[2][4], al[2][4];
#pragma unroll
            for (int mf = 0; mf < 2; mf++) {
                int r0 = rb * 32 + mf * 16 + g;
                ah[mf][0] = *(const unsigned*)&ash[r0][c0];
                ah[mf][1] = *(const unsigned*)&ash[r0 + 8][c0];
                ah[mf][2] = *(const unsigned*)&ash[r0][c0 + 8];
                ah[mf][3] = *(const unsigned*)&ash[r0 + 8][c0 + 8];
                al[mf][0] = *(const unsigned*)&asl[r0][c0];
                al[mf][1] = *(const unsigned*)&asl[r0 + 8][c0];
                al[mf][2] = *(const unsigned*)&asl[r0][c0 + 8];
                al[mf][3] = *(const unsigned*)&asl[r0 + 8][c0 + 8];
            }
#pragma unroll
            for (int j = 0; j < 4; j++) {
                uint4 B = g_bfrag_mlp2[(size_t)(k16 * 8 + cb * 4 + j) * 32 + lane];
#pragma unroll
                for (int mf = 0; mf < 2; mf++) {
                    float* d = acc[mf][j];
                    mma_bf16(d[0], d[1], d[2], d[3], ah[mf][0], ah[mf][1], ah[mf][2], ah[mf][3], B.x, B.y);
                    mma_bf16(d[0], d[1], d[2], d[3], al[mf][0], al[mf][1], al[mf][2], al[mf][3], B.x, B.y);
                    mma_bf16(d[0], d[1], d[2], d[3], ah[mf][0], ah[mf][1], ah[mf][2], ah[mf][3], B.z, B.w);
                }
            }
        }
        __syncthreads();
    }

#pragma unroll
    for (int mf = 0; mf < 2; mf++) {
        int r = n0 + rb * 32 + mf * 16 + g;
#pragma unroll
        for (int j = 0; j < 4; j++) {
            int c = cb * 32 + j * 8 + 2 * t4;
            float* d = acc[mf][j];
            if (r < n)     *(float2*)&outp[(size_t)r * H + c]       = make_float2(d[0], d[1]);
            if (r + 8 < n) *(float2*)&outp[(size_t)(r + 8) * H + c] = make_float2(d[2], d[3]);
        }
    }
}

// =====================================================================
extern "C" void kernel_launch(void* const* d_in, const int* in_sizes, int n_in,
                              void* d_out, int out_size)
{
    const float* x      = (const float*)d_in[0];
    const float* ea     = (const float*)d_in[1];
    const float* w_src  = (const float*)d_in[2];
    const float* w_dst  = (const float*)d_in[3];
    const float* w_edge = (const float*)d_in[4];
    const float* w1     = (const float*)d_in[5];
    const float* gamma  = (const float*)d_in[6];
    const float* beta   = (const float*)d_in[7];
    const float* w2     = (const float*)d_in[8];
    const int*   ei     = (const int*)d_in[9];
    const int*   nbr    = (const int*)d_in[10];
    float* outp = (float*)d_out;

    int n = in_sizes[0] / INC;
    if (n > MAXN) n = MAXN;

    int gb128 = (n + 127) / 128;
    prep_kernel <<<34, 256>>>(w_src, w_dst, w_edge, w2, w1);
    proj_kernel <<<gb128, 256>>>(x, n);
    edge_kernel <<<(n + 3) / 4, 256>>>(ea, ei, nbr, n);
    mlp1_kernel <<<gb128, 256>>>(n);
    fold1_kernel<<<64, 128>>>(gb128);
    fstats_kernel<<<1, 1024>>>(gamma, beta, n);
    mlp2_kernel <<<gb128, 256>>>(outp, n);
}